// round 8
// baseline (speedup 1.0000x reference)
#include <cuda_runtime.h>

// QNNClassifier: 14-qubit statevector, BATCH=2048, DEPTH=8.
// One CTA/batch element; state = QDIM packed (re,im) u64 in smem (128 KB).
// CX deferred as GF(2) relabeling; per layer gates grouped 4+4+4+2 (same
// sigma frame => W=I). Pass = diagonal RZ-phase stage (PACKED f32x2 complex
// multiply, constants from a full 16-entry lane-replicated table indexed
// directly by h=g^bb -> 2 fma-pipe ops/slot, bank-conflict-free) + RY stage
// as 3-shear butterflies (3 fma2/pair, exact).

#define NQ       14
#define QDIM     16384
#define DEPTH    8
#define NGATES   (DEPTH * NQ)   // 112
#define NPASSES  (DEPTH * 4)    // 32
#define NTHREADS 1024

typedef unsigned long long u64;
typedef unsigned int u32;

struct __align__(16) Consts {
    float2 Pcs[NPASSES][16];    // phase (cos, sin) for slot-parity h = 0..15
    int    piv[NPASSES][4];     // sorted pivot bits
    int    V[NPASSES][16];      // coset XOR offsets over slot index
    int    F[NPASSES][4];       // parity masks per gate
    float  tq[NPASSES][4];      // tan(ty/4)  (shear constant)
    float  sy[NPASSES][4];      // sin(ty/2)
    int    fixTab[NPASSES][16]; // low-nibble bank fixup
    int    fixShift[NPASSES];
    int    ffin;
};
__device__ Consts dC;

// ---------------- setup kernel (512 threads, 1 block) ----------------
__global__ void qnn_setup(const float* __restrict__ params)
{
    __shared__ int vg[NGATES], fg[NGATES];
    const int tid = threadIdx.x;

    if (tid == 0) {
        int v[NQ], f[NQ];
        #pragma unroll
        for (int q = 0; q < NQ; ++q) { v[q] = 1 << (NQ - 1 - q); f[q] = v[q]; }
        for (int l = 0; l < DEPTH; ++l) {
            for (int q = 0; q < NQ; ++q) { fg[l * NQ + q] = f[q]; vg[l * NQ + q] = v[q]; }
            for (int c = 0; c < NQ; ++c) {          // CX ring after the layer
                int t = (c + 1) % NQ;
                v[c] ^= v[t];
                f[t] ^= f[c];
            }
        }
        dC.ffin = f[0];
    }
    __syncthreads();

    if (tid < NGATES) {                              // RY shear constants
        int l = tid / NQ, q = tid % NQ;
        int grp = q >> 2; if (grp > 3) grp = 3;
        int p = l * 4 + grp, i = q - grp * 4;
        float ty = params[2 * tid + 1];
        dC.tq[p][i] = tanf(0.25f * ty);
        dC.sy[p][i] = sinf(0.5f * ty);
        dC.F[p][i]  = fg[tid];
    }

    if (tid < NPASSES) {                             // pass geometry
        int l = tid >> 2, grp = tid & 3;
        int cnt = (grp == 3) ? 2 : 4;
        int m[4] = {0, 0, 0, 0};
        for (int i = 0; i < cnt; ++i) m[i] = vg[l * NQ + grp * 4 + i];

        // GF(2) elimination; prefer pivot bits >= 4 (bank-friendly)
        int u[4], bp[4];
        for (int i = 0; i < cnt; ++i) {
            u[i] = m[i];
            for (int j = 0; j < i; ++j)
                if ((u[i] >> bp[j]) & 1) u[i] ^= u[j];
            int hi = u[i] & ~0xF;
            bp[i] = hi ? (31 - __clz(hi)) : (31 - __clz(u[i]));
            for (int j = 0; j < i; ++j)
                if ((u[j] >> bp[i]) & 1) u[j] ^= u[i];
        }
        for (int a = 0; a < cnt - 1; ++a)            // sort ascending
            for (int bq = 0; bq < cnt - 1 - a; ++bq)
                if (bp[bq] > bp[bq + 1]) { int t = bp[bq]; bp[bq] = bp[bq + 1]; bp[bq + 1] = t; }
        for (int i = 0; i < 4; ++i) dC.piv[tid][i] = (i < cnt) ? bp[i] : 30;

        int V[16]; V[0] = 0;
        for (int t = 1; t < (1 << cnt); ++t) V[t] = V[t & (t - 1)] ^ m[__ffs(t) - 1];
        for (int t = 0; t < 16; ++t) dC.V[tid][t] = (t < (1 << cnt)) ? V[t] : 0;

        // low-nibble fixup: copy spare p-bits into pivot positions < 4
        int lowPiv[4], k = 0;
        for (int i = 0; i < cnt; ++i)
            if (bp[i] < 4) lowPiv[k++] = bp[i];
        dC.fixShift[tid] = 4 - k;
        for (int v = 0; v < 16; ++v) {
            int fv = 0;
            for (int i = 0; i < k; ++i)
                if ((v >> i) & 1) fv |= 1 << lowPiv[i];
            dC.fixTab[tid][v] = fv;
        }
    }

    // phase table: Pcs[p][h] = (cos, sin) of phi(h) = sum_i (h_i? +:-) tz_i/2
    if (tid < NPASSES * 16) {
        int p = tid >> 4, h = tid & 15;
        int l = p >> 2, grp = p & 3;
        int cnt = (grp == 3) ? 2 : 4;
        float phi = 0.0f;
        for (int i = 0; i < cnt; ++i) {
            float tz = params[2 * (l * NQ + grp * 4 + i)];
            phi += ((h >> i) & 1) ? 0.5f * tz : -0.5f * tz;
        }
        float s, c;
        sincosf(phi, &s, &c);
        dC.Pcs[p][h] = make_float2(c, s);
    }
}

// ---------------- helpers ----------------
__device__ __forceinline__ u64 fma2(u64 a, u64 b, u64 c) {
    u64 d; asm("fma.rn.f32x2 %0, %1, %2, %3;" : "=l"(d) : "l"(a), "l"(b), "l"(c));
    return d;
}
__device__ __forceinline__ u64 mul2(u64 a, u64 b) {
    u64 d; asm("mul.rn.f32x2 %0, %1, %2;" : "=l"(d) : "l"(a), "l"(b));
    return d;
}
__device__ __forceinline__ u64 splatf(float v) {
    u64 d; asm("mov.b64 %0, {%1, %1};" : "=l"(d) : "f"(v));
    return d;
}
__device__ __forceinline__ u64 splat_sgn(float v, u32 sb) {
    u32 b = __float_as_uint(v) ^ sb;
    return ((u64)b << 32) | (u64)b;
}
// kplus(x) = (-im, re)
__device__ __forceinline__ u64 kplus(u64 x) {
    u64 r;
    asm("{\n\t.reg .b32 l,h;\n\t"
        "mov.b64 {l,h}, %1;\n\t"
        "xor.b32 h, h, 0x80000000;\n\t"
        "mov.b64 %0, {h, l};\n\t}" : "=l"(r) : "l"(x));
    return r;
}

__device__ __forceinline__ int expand4(int p, const int* bp)
{
    #pragma unroll
    for (int i = 0; i < 4; ++i) {
        int m = (1 << bp[i]) - 1;
        p = ((p & ~m) << 1) | (p & m);
    }
    return p;
}
__device__ __forceinline__ int expand2(int p, const int* bp)
{
    #pragma unroll
    for (int i = 0; i < 2; ++i) {
        int m = (1 << bp[i]) - 1;
        p = ((p & ~m) << 1) | (p & m);
    }
    return p;
}

// ---------------- main kernel ----------------
__global__ __launch_bounds__(NTHREADS, 1)
void qnn_kernel(const float* __restrict__ x, float* __restrict__ out)
{
    extern __shared__ u64 sAmp[];                  // [QDIM] packed (re,im)

    __shared__ Consts sC;
    __shared__ float2 repT[2][16][16];             // lane-replicated phase tables
    __shared__ float cq[NQ], sq[NQ];
    __shared__ float tabLo[128], tabHi[128];
    __shared__ float redbuf[NTHREADS / 32];

    const int tid    = threadIdx.x;
    const int lane16 = tid & 15;
    const int b      = blockIdx.x;

    {   // copy constants to smem
        const int n = (int)(sizeof(Consts) / 4);
        const int* src = (const int*)&dC;
        int* dst = (int*)&sC;
        for (int i = tid; i < n; i += NTHREADS) dst[i] = src[i];
    }

    if (tid < NQ) {
        float ang = x[b * NQ + tid] * 1.57079632679489662f;
        float s, c;
        sincosf(ang, &s, &c);
        cq[tid] = c;
        sq[tid] = s;
    }
    __syncthreads();

    // product-state tables (initial RY layer on |0...0>)
    if (tid < 128) {
        float p = 1.0f;
        #pragma unroll
        for (int k = 0; k < 7; ++k)
            p *= ((tid >> k) & 1) ? sq[NQ - 1 - k] : cq[NQ - 1 - k];
        tabLo[tid] = p;
    } else if (tid < 256) {
        int m = tid - 128;
        float p = 1.0f;
        #pragma unroll
        for (int k = 0; k < 7; ++k)
            p *= ((m >> k) & 1) ? sq[6 - k] : cq[6 - k];
        tabHi[m] = p;
    } else if (tid < 512) {
        int e = (tid - 256) >> 4, l = tid & 15;    // prefill phase table pass 0
        repT[0][e][l] = sC.Pcs[0][e];
    }
    __syncthreads();

    #pragma unroll
    for (int k = 0; k < QDIM / NTHREADS; ++k) {
        int j = tid + k * NTHREADS;
        sAmp[j] = (u64)__float_as_uint(tabHi[j >> 7] * tabLo[j & 127]);
    }

    // ---- 32 passes (per layer: 4,4,4 then 2 gates) ----
    for (int p = 0; p < NPASSES; ++p) {
        __syncthreads();
        const int pb = p & 1;

        // fill next pass's replicated phase table (double-buffered)
        if (tid < 256 && p + 1 < NPASSES) {
            int e = tid >> 4, l = tid & 15;
            repT[pb ^ 1][e][l] = sC.Pcs[p + 1][e];
        }

        if ((p & 3) != 3) {
            // ======== 4-gate pass: one 16-amp coset per thread ========
            int mk[4];
            #pragma unroll
            for (int i = 0; i < 4; ++i) mk[i] = sC.V[p][1 << i];

            int jb = expand4(tid, sC.piv[p]);
            jb ^= sC.fixTab[p][(tid >> sC.fixShift[p]) & 15];

            int bb = 0;
            #pragma unroll
            for (int g = 0; g < 4; ++g)
                bb |= (__popc(sC.F[p][g] & jb) & 1) << g;

            // Gray-order load + packed phase multiply  a *= (c + i s)
            u64 A[16];
            {
                int j = jb;
                #pragma unroll
                for (int s = 0; s < 16; ++s) {
                    const int g = s ^ (s >> 1);
                    u64 a = sAmp[j];
                    float2 z = repT[pb][g ^ bb][lane16];
                    A[g] = fma2(kplus(a), splatf(z.y), mul2(a, splatf(z.x)));
                    if (s < 15) {
                        const int c = ((s + 1) & 1) ? 0 : (((s + 1) & 2) ? 1 : (((s + 1) & 4) ? 2 : 3));
                        j ^= mk[c];
                    }
                }
            }

            // 4 RY gates as 3-shear butterflies
            #pragma unroll
            for (int i = 0; i < 4; ++i) {
                const u32 sg   = ((u32)((bb >> i) & 1)) << 31;
                const u64 tnv  = splat_sgn(sC.tq[p][i], sg ^ 0x80000000u);  // -t (role-signed)
                const u64 sv   = splat_sgn(sC.sy[p][i], sg);                //  s (role-signed)

                #pragma unroll
                for (int t = 0; t < 16; ++t) {
                    if (t & (1 << i)) continue;
                    const int t1 = t | (1 << i);
                    u64 Av = A[t], Bv = A[t1];
                    Av = fma2(Bv, tnv, Av);     // x1 = A - t*B
                    Bv = fma2(Av, sv,  Bv);     // y1 = B + s*x1
                    Av = fma2(Bv, tnv, Av);     // x2 = x1 - t*y1
                    A[t] = Av; A[t1] = Bv;
                }
            }

            // Gray-order store
            {
                int j = jb;
                #pragma unroll
                for (int s = 0; s < 16; ++s) {
                    const int g = s ^ (s >> 1);
                    sAmp[j] = A[g];
                    if (s < 15) {
                        const int c = ((s + 1) & 1) ? 0 : (((s + 1) & 2) ? 1 : (((s + 1) & 4) ? 2 : 3));
                        j ^= mk[c];
                    }
                }
            }
        } else {
            // ======== 2-gate pass: four 4-amp cosets per thread ========
            const int m0 = sC.V[p][1], m1 = sC.V[p][2], m01 = sC.V[p][3];
            const int f0 = sC.F[p][0], f1 = sC.F[p][1];
            const int fsh = sC.fixShift[p];
            const float tq0 = sC.tq[p][0], sy0 = sC.sy[p][0];
            const float tq1 = sC.tq[p][1], sy1 = sC.sy[p][1];

            #pragma unroll
            for (int kk = 0; kk < 4; ++kk) {
                const int pp = tid + kk * NTHREADS;
                int jb = expand2(pp, sC.piv[p]);
                jb ^= sC.fixTab[p][(pp >> fsh) & 15];

                const int b0 = __popc(f0 & jb) & 1;
                const int b1 = __popc(f1 & jb) & 1;
                const int bb = b0 | (b1 << 1);

                const int j0 = jb, j1 = jb ^ m0, j2 = jb ^ m1, j3 = jb ^ m01;
                u64 a[4] = { sAmp[j0], sAmp[j1], sAmp[j2], sAmp[j3] };

                #pragma unroll
                for (int g = 0; g < 4; ++g) {
                    float2 z = repT[pb][g ^ bb][lane16];
                    a[g] = fma2(kplus(a[g]), splatf(z.y), mul2(a[g], splatf(z.x)));
                }

                {   // gate 0: pairs (0,1),(2,3)
                    const u32 sg  = ((u32)b0) << 31;
                    const u64 tnv = splat_sgn(tq0, sg ^ 0x80000000u);
                    const u64 sv  = splat_sgn(sy0, sg);
                    a[0] = fma2(a[1], tnv, a[0]); a[1] = fma2(a[0], sv, a[1]); a[0] = fma2(a[1], tnv, a[0]);
                    a[2] = fma2(a[3], tnv, a[2]); a[3] = fma2(a[2], sv, a[3]); a[2] = fma2(a[3], tnv, a[2]);
                }
                {   // gate 1: pairs (0,2),(1,3)
                    const u32 sg  = ((u32)b1) << 31;
                    const u64 tnv = splat_sgn(tq1, sg ^ 0x80000000u);
                    const u64 sv  = splat_sgn(sy1, sg);
                    a[0] = fma2(a[2], tnv, a[0]); a[2] = fma2(a[0], sv, a[2]); a[0] = fma2(a[2], tnv, a[0]);
                    a[1] = fma2(a[3], tnv, a[1]); a[3] = fma2(a[1], sv, a[3]); a[1] = fma2(a[3], tnv, a[1]);
                }

                sAmp[j0] = a[0]; sAmp[j1] = a[1]; sAmp[j2] = a[2]; sAmp[j3] = a[3];
            }
        }
    }
    __syncthreads();

    // ---- expectation value ----
    const int ff = sC.ffin;
    const float2* sF2 = (const float2*)sAmp;
    float acc = 0.0f;
    #pragma unroll
    for (int k = 0; k < QDIM / NTHREADS; ++k) {
        int j = tid + k * NTHREADS;
        float2 a = sF2[j];
        float pr = a.x * a.x + a.y * a.y;
        acc += (__popc(ff & j) & 1) ? -pr : pr;
    }
    #pragma unroll
    for (int off = 16; off > 0; off >>= 1)
        acc += __shfl_down_sync(0xffffffffu, acc, off);
    if ((tid & 31) == 0) redbuf[tid >> 5] = acc;
    __syncthreads();
    if (tid < 32) {
        float t = redbuf[tid];
        #pragma unroll
        for (int off = 16; off > 0; off >>= 1)
            t += __shfl_down_sync(0xffffffffu, t, off);
        if (tid == 0) out[b] = (t + 1.0f) * 0.5f;
    }
}

extern "C" void kernel_launch(void* const* d_in, const int* in_sizes, int n_in,
                              void* d_out, int out_size)
{
    const float* x      = (const float*)d_in[0];   // (2048, 14)
    const float* params = (const float*)d_in[1];   // (224,)
    float* out          = (float*)d_out;           // (2048,)
    (void)in_sizes; (void)n_in;

    qnn_setup<<<1, 512>>>(params);

    const size_t shmem = (size_t)QDIM * sizeof(u64);   // 128 KB
    cudaFuncSetAttribute(qnn_kernel,
                         cudaFuncAttributeMaxDynamicSharedMemorySize,
                         (int)shmem);
    qnn_kernel<<<out_size, NTHREADS, shmem>>>(x, out);
}

// round 9
// speedup vs baseline: 1.1076x; 1.1076x over previous
#include <cuda_runtime.h>

// QNNClassifier: 14-qubit statevector, BATCH=2048, DEPTH=8.
// One CTA/batch element; state = QDIM packed (re,im) u64 in smem (128 KB).
// CX deferred as GF(2) relabeling; per layer gates grouped 4+4+4+2 (same
// sigma frame => W=I). RZ phases are generated ON THE FLY by a Gray-code
// walk of a unit complex z (one 4-FFMA update per step, conj symmetry halves
// the walk) -- no phase table, no table LDS, no index math. RY gates are
// 3-shear packed-f32x2 butterflies (3 fma2/pair, exact), roles folded into
// sign bits of the constants. Coset addressing is bank-conflict-free.

#define NQ       14
#define QDIM     16384
#define DEPTH    8
#define NGATES   (DEPTH * NQ)   // 112
#define NPASSES  (DEPTH * 4)    // 32
#define NTHREADS 1024

typedef unsigned long long u64;
typedef unsigned int u32;

struct __align__(16) Consts {
    int    piv[NPASSES][4];     // sorted pivot bits
    int    V[NPASSES][16];      // coset XOR offsets over slot index
    int    F[NPASSES][4];       // parity masks per gate
    float  tq[NPASSES][4];      // tan(ty/4)  (shear constant)
    float  sy[NPASSES][4];      // sin(ty/2)
    float  czH[NPASSES][4];     // cos(tz/2)
    float  szH[NPASSES][4];     // sin(tz/2)
    float  czF[NPASSES][4];     // cos(tz)
    float  szF[NPASSES][4];     // sin(tz)
    int    fixTab[NPASSES][16]; // low-nibble bank fixup
    int    fixShift[NPASSES];
    int    ffin;
};
__device__ Consts dC;

// ---------------- setup kernel (512 threads, 1 block) ----------------
__global__ void qnn_setup(const float* __restrict__ params)
{
    __shared__ int vg[NGATES], fg[NGATES];
    const int tid = threadIdx.x;

    if (tid == 0) {
        int v[NQ], f[NQ];
        #pragma unroll
        for (int q = 0; q < NQ; ++q) { v[q] = 1 << (NQ - 1 - q); f[q] = v[q]; }
        for (int l = 0; l < DEPTH; ++l) {
            for (int q = 0; q < NQ; ++q) { fg[l * NQ + q] = f[q]; vg[l * NQ + q] = v[q]; }
            for (int c = 0; c < NQ; ++c) {          // CX ring after the layer
                int t = (c + 1) % NQ;
                v[c] ^= v[t];
                f[t] ^= f[c];
            }
        }
        dC.ffin = f[0];
    }
    __syncthreads();

    if (tid < NGATES) {                              // per-gate constants
        int l = tid / NQ, q = tid % NQ;
        int grp = q >> 2; if (grp > 3) grp = 3;
        int p = l * 4 + grp, i = q - grp * 4;
        float tz = params[2 * tid];
        float ty = params[2 * tid + 1];
        dC.tq[p][i] = tanf(0.25f * ty);
        dC.sy[p][i] = sinf(0.5f * ty);
        float sH, cH, sF, cF;
        sincosf(0.5f * tz, &sH, &cH);
        sincosf(tz, &sF, &cF);
        dC.czH[p][i] = cH; dC.szH[p][i] = sH;
        dC.czF[p][i] = cF; dC.szF[p][i] = sF;
        dC.F[p][i]   = fg[tid];
    }

    if (tid < NPASSES) {                             // pass geometry
        int l = tid >> 2, grp = tid & 3;
        int cnt = (grp == 3) ? 2 : 4;
        int m[4] = {0, 0, 0, 0};
        for (int i = 0; i < cnt; ++i) m[i] = vg[l * NQ + grp * 4 + i];

        // GF(2) elimination; prefer pivot bits >= 4 (bank-friendly)
        int u[4], bp[4];
        for (int i = 0; i < cnt; ++i) {
            u[i] = m[i];
            for (int j = 0; j < i; ++j)
                if ((u[i] >> bp[j]) & 1) u[i] ^= u[j];
            int hi = u[i] & ~0xF;
            bp[i] = hi ? (31 - __clz(hi)) : (31 - __clz(u[i]));
            for (int j = 0; j < i; ++j)
                if ((u[j] >> bp[i]) & 1) u[j] ^= u[i];
        }
        for (int a = 0; a < cnt - 1; ++a)            // sort ascending
            for (int bq = 0; bq < cnt - 1 - a; ++bq)
                if (bp[bq] > bp[bq + 1]) { int t = bp[bq]; bp[bq] = bp[bq + 1]; bp[bq + 1] = t; }
        for (int i = 0; i < 4; ++i) dC.piv[tid][i] = (i < cnt) ? bp[i] : 30;

        int V[16]; V[0] = 0;
        for (int t = 1; t < (1 << cnt); ++t) V[t] = V[t & (t - 1)] ^ m[__ffs(t) - 1];
        for (int t = 0; t < 16; ++t) dC.V[tid][t] = (t < (1 << cnt)) ? V[t] : 0;

        // low-nibble fixup: copy spare p-bits into pivot positions < 4
        int lowPiv[4], k = 0;
        for (int i = 0; i < cnt; ++i)
            if (bp[i] < 4) lowPiv[k++] = bp[i];
        dC.fixShift[tid] = 4 - k;
        for (int v = 0; v < 16; ++v) {
            int fv = 0;
            for (int i = 0; i < k; ++i)
                if ((v >> i) & 1) fv |= 1 << lowPiv[i];
            dC.fixTab[tid][v] = fv;
        }
    }
}

// ---------------- helpers ----------------
__device__ __forceinline__ u64 fma2(u64 a, u64 b, u64 c) {
    u64 d; asm("fma.rn.f32x2 %0, %1, %2, %3;" : "=l"(d) : "l"(a), "l"(b), "l"(c));
    return d;
}
__device__ __forceinline__ u64 pk(float lo, float hi) {
    u64 d; asm("mov.b64 %0, {%1, %2};" : "=l"(d) : "f"(lo), "f"(hi));
    return d;
}
__device__ __forceinline__ u64 splat_sgn(float v, u32 sb) {
    u32 b = __float_as_uint(v) ^ sb;
    return ((u64)b << 32) | (u64)b;
}
__device__ __forceinline__ float fsgn(float v, u32 sb) {   // sign-fold scalar
    return __int_as_float(__float_as_int(v) ^ sb);
}

__device__ __forceinline__ int expand4(int p, const int* bp)
{
    #pragma unroll
    for (int i = 0; i < 4; ++i) {
        int m = (1 << bp[i]) - 1;
        p = ((p & ~m) << 1) | (p & m);
    }
    return p;
}
__device__ __forceinline__ int expand2(int p, const int* bp)
{
    #pragma unroll
    for (int i = 0; i < 2; ++i) {
        int m = (1 << bp[i]) - 1;
        p = ((p & ~m) << 1) | (p & m);
    }
    return p;
}

// ---------------- main kernel ----------------
__global__ __launch_bounds__(NTHREADS, 1)
void qnn_kernel(const float* __restrict__ x, float* __restrict__ out)
{
    extern __shared__ u64 sAmp[];                  // [QDIM] packed (re,im)
    float2* sF2 = (float2*)sAmp;

    __shared__ Consts sC;
    __shared__ float cq[NQ], sq[NQ];
    __shared__ float tabLo[128], tabHi[128];
    __shared__ float redbuf[NTHREADS / 32];

    const int tid = threadIdx.x;
    const int b   = blockIdx.x;

    {   // copy constants to smem
        const int n = (int)(sizeof(Consts) / 4);
        const int* src = (const int*)&dC;
        int* dst = (int*)&sC;
        for (int i = tid; i < n; i += NTHREADS) dst[i] = src[i];
    }

    if (tid < NQ) {
        float ang = x[b * NQ + tid] * 1.57079632679489662f;
        float s, c;
        sincosf(ang, &s, &c);
        cq[tid] = c;
        sq[tid] = s;
    }
    __syncthreads();

    // product-state tables (initial RY layer on |0...0>)
    if (tid < 128) {
        float p = 1.0f;
        #pragma unroll
        for (int k = 0; k < 7; ++k)
            p *= ((tid >> k) & 1) ? sq[NQ - 1 - k] : cq[NQ - 1 - k];
        tabLo[tid] = p;
    } else if (tid < 256) {
        int m = tid - 128;
        float p = 1.0f;
        #pragma unroll
        for (int k = 0; k < 7; ++k)
            p *= ((m >> k) & 1) ? sq[6 - k] : cq[6 - k];
        tabHi[m] = p;
    }
    __syncthreads();

    #pragma unroll
    for (int k = 0; k < QDIM / NTHREADS; ++k) {
        int j = tid + k * NTHREADS;
        sAmp[j] = (u64)__float_as_uint(tabHi[j >> 7] * tabLo[j & 127]);
    }

    // ---- 32 passes (per layer: 4,4,4 then 2 gates) ----
    for (int p = 0; p < NPASSES; ++p) {
        __syncthreads();

        if ((p & 3) != 3) {
            // ======== 4-gate pass: one 16-amp coset per thread ========
            int mk[4];
            #pragma unroll
            for (int i = 0; i < 4; ++i) mk[i] = sC.V[p][1 << i];
            const int V15 = mk[0] ^ mk[1] ^ mk[2] ^ mk[3];

            int jb = expand4(tid, sC.piv[p]);
            jb ^= sC.fixTab[p][(tid >> sC.fixShift[p]) & 15];

            int bb = 0;
            #pragma unroll
            for (int g = 0; g < 4; ++g)
                bb |= (__popc(sC.F[p][g] & jb) & 1) << g;

            // z0 = P(bb): product of role-signed half-angle factors (c, -s~)
            float zr, zi;
            {
                zr = sC.czH[p][0];
                zi = -fsgn(sC.szH[p][0], (u32)(bb & 1) << 31);
                #pragma unroll
                for (int k = 1; k < 4; ++k) {
                    float c  = sC.czH[p][k];
                    float sn = -fsgn(sC.szH[p][k], (u32)((bb >> k) & 1) << 31);
                    float t  = zr * c - zi * sn;
                    zi = zi * c + zr * sn;
                    zr = t;
                }
            }
            // full-angle step constants (gates 0..2), role-signed
            float cF0 = sC.czF[p][0], sF0 = fsgn(sC.szF[p][0], (u32)(bb & 1) << 31);
            float cF1 = sC.czF[p][1], sF1 = fsgn(sC.szF[p][1], (u32)((bb >> 1) & 1) << 31);
            float cF2 = sC.czF[p][2], sF2c = fsgn(sC.szF[p][2], (u32)((bb >> 2) & 1) << 31);

            // dual Gray walk over u=0..7 (slot g and partner g^15), applying
            // z to slot g and conj(z) to slot g^15
            u64 A[16];
            {
                int j = jb;
                #pragma unroll
                for (int u = 0; u < 8; ++u) {
                    const int g = u ^ (u >> 1);                 // bit3 == 0
                    float2 a = sF2[j];
                    float2 c2 = sF2[j ^ V15];
                    A[g]      = pk(a.x * zr - a.y * zi,  a.y * zr + a.x * zi);
                    A[g ^ 15] = pk(c2.x * zr + c2.y * zi, c2.y * zr - c2.x * zi);
                    if (u < 8 - 1) {
                        const int un = u + 1;
                        const int c  = (un & 1) ? 0 : ((un & 2) ? 1 : 2);
                        const int gn = (un ^ (un >> 1)) >> c & 1;   // new bit value
                        float cc = (c == 0) ? cF0 : (c == 1) ? cF1 : cF2;
                        float ss = (c == 0) ? sF0 : (c == 1) ? sF1 : sF2c;
                        if (!gn) ss = -ss;
                        float t = zr * cc - zi * ss;
                        zi = zi * cc + zr * ss;
                        zr = t;
                        j ^= mk[c];
                    }
                }
            }

            // 4 RY gates as 3-shear butterflies
            #pragma unroll
            for (int i = 0; i < 4; ++i) {
                const u32 sg   = ((u32)((bb >> i) & 1)) << 31;
                const u64 tnv  = splat_sgn(sC.tq[p][i], sg ^ 0x80000000u);  // -t (role-signed)
                const u64 sv   = splat_sgn(sC.sy[p][i], sg);                //  s (role-signed)

                #pragma unroll
                for (int t = 0; t < 16; ++t) {
                    if (t & (1 << i)) continue;
                    const int t1 = t | (1 << i);
                    u64 Av = A[t], Bv = A[t1];
                    Av = fma2(Bv, tnv, Av);     // x1 = A - t*B
                    Bv = fma2(Av, sv,  Bv);     // y1 = B + s*x1
                    Av = fma2(Bv, tnv, Av);     // x2 = x1 - t*y1
                    A[t] = Av; A[t1] = Bv;
                }
            }

            // dual Gray store
            {
                int j = jb;
                #pragma unroll
                for (int u = 0; u < 8; ++u) {
                    const int g = u ^ (u >> 1);
                    sAmp[j]       = A[g];
                    sAmp[j ^ V15] = A[g ^ 15];
                    if (u < 8 - 1) {
                        const int un = u + 1;
                        const int c  = (un & 1) ? 0 : ((un & 2) ? 1 : 2);
                        j ^= mk[c];
                    }
                }
            }
        } else {
            // ======== 2-gate pass: four 4-amp cosets per thread ========
            const int m0 = sC.V[p][1], m1 = sC.V[p][2], m01 = sC.V[p][3];
            const int f0 = sC.F[p][0], f1 = sC.F[p][1];
            const int fsh = sC.fixShift[p];
            const float tq0 = sC.tq[p][0], sy0 = sC.sy[p][0];
            const float tq1 = sC.tq[p][1], sy1 = sC.sy[p][1];
            const float ca = sC.czH[p][0], cb = sC.czH[p][1];
            const float saM = sC.szH[p][0], sbM = sC.szH[p][1];

            #pragma unroll
            for (int kk = 0; kk < 4; ++kk) {
                const int pp = tid + kk * NTHREADS;
                int jb = expand2(pp, sC.piv[p]);
                jb ^= sC.fixTab[p][(pp >> fsh) & 15];

                const int b0 = __popc(f0 & jb) & 1;
                const int b1 = __popc(f1 & jb) & 1;

                // role-signed half-angle sines
                const float sa = fsgn(saM, (u32)b0 << 31);
                const float sb = fsgn(sbM, (u32)b1 << 31);
                // phase components for the 4 slots (static signs, conj pairs)
                const float X = ca * cb, Y = sa * sb, U = sa * cb, Vv = ca * sb;
                const float rA = X - Y, rB = X + Y;     // cos(-a-b), cos(a-b)
                const float iA = U + Vv, iB = Vv - U;   // |sin| combos

                const int j0 = jb, j1 = jb ^ m0, j2 = jb ^ m1, j3 = jb ^ m01;
                float2 x0 = sF2[j0], x1 = sF2[j1], x2 = sF2[j2], x3 = sF2[j3];

                // a0: z=(rA,-iA)  a1: z=(rB,-iB)  a2: z=(rB,+iB)  a3: z=(rA,+iA)
                u64 a0 = pk(x0.x * rA + x0.y * iA, x0.y * rA - x0.x * iA);
                u64 a1 = pk(x1.x * rB + x1.y * iB, x1.y * rB - x1.x * iB);
                u64 a2 = pk(x2.x * rB - x2.y * iB, x2.y * rB + x2.x * iB);
                u64 a3 = pk(x3.x * rA - x3.y * iA, x3.y * rA + x3.x * iA);

                {   // gate 0: pairs (0,1),(2,3)
                    const u32 sg  = ((u32)b0) << 31;
                    const u64 tnv = splat_sgn(tq0, sg ^ 0x80000000u);
                    const u64 sv  = splat_sgn(sy0, sg);
                    a0 = fma2(a1, tnv, a0); a1 = fma2(a0, sv, a1); a0 = fma2(a1, tnv, a0);
                    a2 = fma2(a3, tnv, a2); a3 = fma2(a2, sv, a3); a2 = fma2(a3, tnv, a2);
                }
                {   // gate 1: pairs (0,2),(1,3)
                    const u32 sg  = ((u32)b1) << 31;
                    const u64 tnv = splat_sgn(tq1, sg ^ 0x80000000u);
                    const u64 sv  = splat_sgn(sy1, sg);
                    a0 = fma2(a2, tnv, a0); a2 = fma2(a0, sv, a2); a0 = fma2(a2, tnv, a0);
                    a1 = fma2(a3, tnv, a1); a3 = fma2(a1, sv, a3); a1 = fma2(a3, tnv, a1);
                }

                sAmp[j0] = a0; sAmp[j1] = a1; sAmp[j2] = a2; sAmp[j3] = a3;
            }
        }
    }
    __syncthreads();

    // ---- expectation value ----
    const int ff = sC.ffin;
    float acc = 0.0f;
    #pragma unroll
    for (int k = 0; k < QDIM / NTHREADS; ++k) {
        int j = tid + k * NTHREADS;
        float2 a = sF2[j];
        float pr = a.x * a.x + a.y * a.y;
        acc += (__popc(ff & j) & 1) ? -pr : pr;
    }
    #pragma unroll
    for (int off = 16; off > 0; off >>= 1)
        acc += __shfl_down_sync(0xffffffffu, acc, off);
    if ((tid & 31) == 0) redbuf[tid >> 5] = acc;
    __syncthreads();
    if (tid < 32) {
        float t = redbuf[tid];
        #pragma unroll
        for (int off = 16; off > 0; off >>= 1)
            t += __shfl_down_sync(0xffffffffu, t, off);
        if (tid == 0) out[b] = (t + 1.0f) * 0.5f;
    }
}

extern "C" void kernel_launch(void* const* d_in, const int* in_sizes, int n_in,
                              void* d_out, int out_size)
{
    const float* x      = (const float*)d_in[0];   // (2048, 14)
    const float* params = (const float*)d_in[1];   // (224,)
    float* out          = (float*)d_out;           // (2048,)
    (void)in_sizes; (void)n_in;

    qnn_setup<<<1, 512>>>(params);

    const size_t shmem = (size_t)QDIM * sizeof(u64);   // 128 KB
    cudaFuncSetAttribute(qnn_kernel,
                         cudaFuncAttributeMaxDynamicSharedMemorySize,
                         (int)shmem);
    qnn_kernel<<<out_size, NTHREADS, shmem>>>(x, out);
}

// round 10
// speedup vs baseline: 1.4071x; 1.2704x over previous
#include <cuda_runtime.h>

// QNNClassifier: 14-qubit statevector, BATCH=2048, DEPTH=8.
// One CTA/batch element; state = QDIM packed (re,im) u64 in smem (128 KB).
// CX deferred as GF(2) relabeling; per layer gates grouped 5+5+4 (same sigma
// frame => W=I) -> only 24 full-state sweeps (was 32). 512 threads; 5-gate
// passes hold a 32-amp coset in registers, 4-gate passes two 16-amp cosets.
// RZ phases generated on the fly by a Gray-code walk of a unit complex z
// (conj symmetry halves the walk); RY gates are 3-shear packed-f32x2
// butterflies with roles folded into constant sign bits. Coset addressing is
// bank-conflict-free via pivot selection + low-nibble fixup.

#define NQ       14
#define QDIM     16384
#define DEPTH    8
#define NGATES   (DEPTH * NQ)   // 112
#define NPASSES  (DEPTH * 3)    // 24 (5+5+4 per layer)
#define NTHREADS 512

typedef unsigned long long u64;
typedef unsigned int u32;

struct __align__(16) Consts {
    int    piv[NPASSES][5];     // sorted pivot bits (pad 30)
    int    M[NPASSES][5];       // flip masks per gate
    int    F[NPASSES][5];       // parity masks per gate
    float  tq[NPASSES][5];      // tan(ty/4)
    float  sy[NPASSES][5];      // sin(ty/2)
    float  czH[NPASSES][5];     // cos(tz/2)
    float  szH[NPASSES][5];     // sin(tz/2)
    float  czF[NPASSES][5];     // cos(tz)
    float  szF[NPASSES][5];     // sin(tz)
    int    fixTab[NPASSES][16]; // low-nibble bank fixup
    int    fixShift[NPASSES];
    int    ffin;
};
__device__ Consts dC;

// ---------------- setup kernel ----------------
__global__ void qnn_setup(const float* __restrict__ params)
{
    __shared__ int vg[NGATES], fg[NGATES];
    const int tid = threadIdx.x;

    if (tid == 0) {
        int v[NQ], f[NQ];
        #pragma unroll
        for (int q = 0; q < NQ; ++q) { v[q] = 1 << (NQ - 1 - q); f[q] = v[q]; }
        for (int l = 0; l < DEPTH; ++l) {
            for (int q = 0; q < NQ; ++q) { fg[l * NQ + q] = f[q]; vg[l * NQ + q] = v[q]; }
            for (int c = 0; c < NQ; ++c) {          // CX ring after the layer
                int t = (c + 1) % NQ;
                v[c] ^= v[t];
                f[t] ^= f[c];
            }
        }
        dC.ffin = f[0];
    }
    __syncthreads();

    if (tid < NGATES) {                              // per-gate constants
        int l = tid / NQ, q = tid % NQ;
        int grp  = (q < 5) ? 0 : (q < 10) ? 1 : 2;
        int base = (grp == 0) ? 0 : (grp == 1) ? 5 : 10;
        int p = l * 3 + grp, i = q - base;
        float tz = params[2 * tid];
        float ty = params[2 * tid + 1];
        dC.tq[p][i] = tanf(0.25f * ty);
        dC.sy[p][i] = sinf(0.5f * ty);
        float sH, cH, sF, cF;
        sincosf(0.5f * tz, &sH, &cH);
        sincosf(tz, &sF, &cF);
        dC.czH[p][i] = cH; dC.szH[p][i] = sH;
        dC.czF[p][i] = cF; dC.szF[p][i] = sF;
        dC.F[p][i]   = fg[tid];
        dC.M[p][i]   = vg[tid];
    }

    if (tid < NPASSES) {                             // pass geometry
        int l = tid / 3, grp = tid % 3;
        int cnt  = (grp == 2) ? 4 : 5;
        int base = (grp == 0) ? 0 : (grp == 1) ? 5 : 10;
        int m[5] = {0, 0, 0, 0, 0};
        for (int i = 0; i < cnt; ++i) m[i] = vg[l * NQ + base + i];

        // GF(2) elimination; prefer pivot bits >= 4 (bank-friendly)
        int u[5], bp[5];
        for (int i = 0; i < cnt; ++i) {
            u[i] = m[i];
            for (int j = 0; j < i; ++j)
                if ((u[i] >> bp[j]) & 1) u[i] ^= u[j];
            int hi = u[i] & ~0xF;
            bp[i] = hi ? (31 - __clz(hi)) : (31 - __clz(u[i]));
            for (int j = 0; j < i; ++j)
                if ((u[j] >> bp[i]) & 1) u[j] ^= u[i];
        }
        for (int a = 0; a < cnt - 1; ++a)            // sort ascending
            for (int bq = 0; bq < cnt - 1 - a; ++bq)
                if (bp[bq] > bp[bq + 1]) { int t = bp[bq]; bp[bq] = bp[bq + 1]; bp[bq + 1] = t; }
        for (int i = 0; i < 5; ++i) dC.piv[tid][i] = (i < cnt) ? bp[i] : 30;

        // low-nibble fixup: copy spare rep-bits into pivot positions < 4
        int lowPiv[4], k = 0;
        for (int i = 0; i < cnt; ++i)
            if (bp[i] < 4) lowPiv[k++] = bp[i];
        dC.fixShift[tid] = 4 - k;
        for (int v = 0; v < 16; ++v) {
            int fv = 0;
            for (int i = 0; i < k; ++i)
                if ((v >> i) & 1) fv |= 1 << lowPiv[i];
            dC.fixTab[tid][v] = fv;
        }
    }
}

// ---------------- helpers ----------------
__device__ __forceinline__ u64 fma2(u64 a, u64 b, u64 c) {
    u64 d; asm("fma.rn.f32x2 %0, %1, %2, %3;" : "=l"(d) : "l"(a), "l"(b), "l"(c));
    return d;
}
__device__ __forceinline__ u64 pk(float lo, float hi) {
    u64 d; asm("mov.b64 %0, {%1, %2};" : "=l"(d) : "f"(lo), "f"(hi));
    return d;
}
__device__ __forceinline__ u64 splat_sgn(float v, u32 sb) {
    u32 b = __float_as_uint(v) ^ sb;
    return ((u64)b << 32) | (u64)b;
}
__device__ __forceinline__ float fsgn(float v, u32 sb) {
    return __int_as_float(__float_as_int(v) ^ sb);
}

// insert zero bits at 5 sorted pivot positions (pad pivot 30 = no-op)
__device__ __forceinline__ int expand5(int p, const int* bp)
{
    #pragma unroll
    for (int i = 0; i < 5; ++i) {
        int m = (1 << bp[i]) - 1;
        p = ((p & ~m) << 1) | (p & m);
    }
    return p;
}

// ---------------- main kernel ----------------
__global__ __launch_bounds__(NTHREADS, 1)
void qnn_kernel(const float* __restrict__ x, float* __restrict__ out)
{
    extern __shared__ u64 sAmp[];                  // [QDIM] packed (re,im)
    float2* sF2 = (float2*)sAmp;

    __shared__ Consts sC;
    __shared__ float cq[NQ], sq[NQ];
    __shared__ float tabLo[128], tabHi[128];
    __shared__ float redbuf[NTHREADS / 32];

    const int tid = threadIdx.x;
    const int b   = blockIdx.x;

    {   // copy constants to smem
        const int n = (int)(sizeof(Consts) / 4);
        const int* src = (const int*)&dC;
        int* dst = (int*)&sC;
        for (int i = tid; i < n; i += NTHREADS) dst[i] = src[i];
    }

    if (tid < NQ) {
        float ang = x[b * NQ + tid] * 1.57079632679489662f;
        float s, c;
        sincosf(ang, &s, &c);
        cq[tid] = c;
        sq[tid] = s;
    }
    __syncthreads();

    // product-state tables (initial RY layer on |0...0>)
    if (tid < 128) {
        float p = 1.0f;
        #pragma unroll
        for (int k = 0; k < 7; ++k)
            p *= ((tid >> k) & 1) ? sq[NQ - 1 - k] : cq[NQ - 1 - k];
        tabLo[tid] = p;
    } else if (tid < 256) {
        int m = tid - 128;
        float p = 1.0f;
        #pragma unroll
        for (int k = 0; k < 7; ++k)
            p *= ((m >> k) & 1) ? sq[6 - k] : cq[6 - k];
        tabHi[m] = p;
    }
    __syncthreads();

    #pragma unroll
    for (int k = 0; k < QDIM / NTHREADS; ++k) {
        int j = tid + k * NTHREADS;
        sAmp[j] = (u64)__float_as_uint(tabHi[j >> 7] * tabLo[j & 127]);
    }

    // ---- 24 passes (per layer: 5, 5, 4 gates) ----
    for (int p = 0; p < NPASSES; ++p) {
        __syncthreads();
        const int grp = p - (p / 3) * 3;

        if (grp != 2) {
            // ======== 5-gate pass: one 32-amp coset per thread ========
            int mk[5];
            #pragma unroll
            for (int i = 0; i < 5; ++i) mk[i] = sC.M[p][i];
            const int V31 = mk[0] ^ mk[1] ^ mk[2] ^ mk[3] ^ mk[4];

            int jb = expand5(tid, sC.piv[p]);
            jb ^= sC.fixTab[p][(tid >> sC.fixShift[p]) & 15];

            int bb = 0;
            #pragma unroll
            for (int g = 0; g < 5; ++g)
                bb |= (__popc(sC.F[p][g] & jb) & 1) << g;

            // z0 = P(bb): product of 5 role-signed half-angle factors
            float zr, zi;
            {
                zr = sC.czH[p][0];
                zi = -fsgn(sC.szH[p][0], (u32)(bb & 1) << 31);
                #pragma unroll
                for (int k = 1; k < 5; ++k) {
                    float c  = sC.czH[p][k];
                    float sn = -fsgn(sC.szH[p][k], (u32)((bb >> k) & 1) << 31);
                    float t  = zr * c - zi * sn;
                    zi = zi * c + zr * sn;
                    zr = t;
                }
            }
            // full-angle step constants (walk bits 0..3), role-signed
            float cF0 = sC.czF[p][0], sF0 = fsgn(sC.szF[p][0], (u32)(bb & 1) << 31);
            float cF1 = sC.czF[p][1], sF1 = fsgn(sC.szF[p][1], (u32)((bb >> 1) & 1) << 31);
            float cF2 = sC.czF[p][2], sF2v = fsgn(sC.szF[p][2], (u32)((bb >> 2) & 1) << 31);
            float cF3 = sC.czF[p][3], sF3 = fsgn(sC.szF[p][3], (u32)((bb >> 3) & 1) << 31);

            // dual Gray walk over u=0..15 (slot g, partner g^31), applying
            // z to slot g and conj(z) to slot g^31
            u64 A[32];
            {
                int j = jb;
                #pragma unroll
                for (int u = 0; u < 16; ++u) {
                    const int g = u ^ (u >> 1);                 // bit4 == 0
                    float2 a  = sF2[j];
                    float2 c2 = sF2[j ^ V31];
                    A[g]      = pk(a.x * zr - a.y * zi,  a.y * zr + a.x * zi);
                    A[g ^ 31] = pk(c2.x * zr + c2.y * zi, c2.y * zr - c2.x * zi);
                    if (u < 15) {
                        const int un = u + 1;
                        const int c  = (un & 1) ? 0 : ((un & 2) ? 1 : ((un & 4) ? 2 : 3));
                        const int gn = ((un ^ (un >> 1)) >> c) & 1;
                        float cc = (c == 0) ? cF0 : (c == 1) ? cF1 : (c == 2) ? cF2 : cF3;
                        float ss = (c == 0) ? sF0 : (c == 1) ? sF1 : (c == 2) ? sF2v : sF3;
                        if (!gn) ss = -ss;
                        float t = zr * cc - zi * ss;
                        zi = zi * cc + zr * ss;
                        zr = t;
                        j ^= mk[c];
                    }
                }
            }

            // 5 RY gates as 3-shear butterflies
            #pragma unroll
            for (int i = 0; i < 5; ++i) {
                const u32 sg  = ((u32)((bb >> i) & 1)) << 31;
                const u64 tnv = splat_sgn(sC.tq[p][i], sg ^ 0x80000000u);   // -t
                const u64 sv  = splat_sgn(sC.sy[p][i], sg);                 //  s

                #pragma unroll
                for (int t = 0; t < 32; ++t) {
                    if (t & (1 << i)) continue;
                    const int t1 = t | (1 << i);
                    u64 Av = A[t], Bv = A[t1];
                    Av = fma2(Bv, tnv, Av);
                    Bv = fma2(Av, sv,  Bv);
                    Av = fma2(Bv, tnv, Av);
                    A[t] = Av; A[t1] = Bv;
                }
            }

            // dual Gray store
            {
                int j = jb;
                #pragma unroll
                for (int u = 0; u < 16; ++u) {
                    const int g = u ^ (u >> 1);
                    sAmp[j]       = A[g];
                    sAmp[j ^ V31] = A[g ^ 31];
                    if (u < 15) {
                        const int un = u + 1;
                        const int c  = (un & 1) ? 0 : ((un & 2) ? 1 : ((un & 4) ? 2 : 3));
                        j ^= mk[c];
                    }
                }
            }
        } else {
            // ======== 4-gate pass: two 16-amp cosets per thread ========
            int mk[4];
            #pragma unroll
            for (int i = 0; i < 4; ++i) mk[i] = sC.M[p][i];
            const int V15 = mk[0] ^ mk[1] ^ mk[2] ^ mk[3];
            const int fsh = sC.fixShift[p];

            #pragma unroll
            for (int kk = 0; kk < 2; ++kk) {
                const int pp = tid + kk * NTHREADS;
                int jb = expand5(pp, sC.piv[p]);
                jb ^= sC.fixTab[p][(pp >> fsh) & 15];

                int bb = 0;
                #pragma unroll
                for (int g = 0; g < 4; ++g)
                    bb |= (__popc(sC.F[p][g] & jb) & 1) << g;

                float zr, zi;
                {
                    zr = sC.czH[p][0];
                    zi = -fsgn(sC.szH[p][0], (u32)(bb & 1) << 31);
                    #pragma unroll
                    for (int k = 1; k < 4; ++k) {
                        float c  = sC.czH[p][k];
                        float sn = -fsgn(sC.szH[p][k], (u32)((bb >> k) & 1) << 31);
                        float t  = zr * c - zi * sn;
                        zi = zi * c + zr * sn;
                        zr = t;
                    }
                }
                float cF0 = sC.czF[p][0], sF0 = fsgn(sC.szF[p][0], (u32)(bb & 1) << 31);
                float cF1 = sC.czF[p][1], sF1 = fsgn(sC.szF[p][1], (u32)((bb >> 1) & 1) << 31);
                float cF2 = sC.czF[p][2], sF2v = fsgn(sC.szF[p][2], (u32)((bb >> 2) & 1) << 31);

                u64 A[16];
                {
                    int j = jb;
                    #pragma unroll
                    for (int u = 0; u < 8; ++u) {
                        const int g = u ^ (u >> 1);             // bit3 == 0
                        float2 a  = sF2[j];
                        float2 c2 = sF2[j ^ V15];
                        A[g]      = pk(a.x * zr - a.y * zi,  a.y * zr + a.x * zi);
                        A[g ^ 15] = pk(c2.x * zr + c2.y * zi, c2.y * zr - c2.x * zi);
                        if (u < 7) {
                            const int un = u + 1;
                            const int c  = (un & 1) ? 0 : ((un & 2) ? 1 : 2);
                            const int gn = ((un ^ (un >> 1)) >> c) & 1;
                            float cc = (c == 0) ? cF0 : (c == 1) ? cF1 : cF2;
                            float ss = (c == 0) ? sF0 : (c == 1) ? sF1 : sF2v;
                            if (!gn) ss = -ss;
                            float t = zr * cc - zi * ss;
                            zi = zi * cc + zr * ss;
                            zr = t;
                            j ^= mk[c];
                        }
                    }
                }

                #pragma unroll
                for (int i = 0; i < 4; ++i) {
                    const u32 sg  = ((u32)((bb >> i) & 1)) << 31;
                    const u64 tnv = splat_sgn(sC.tq[p][i], sg ^ 0x80000000u);
                    const u64 sv  = splat_sgn(sC.sy[p][i], sg);

                    #pragma unroll
                    for (int t = 0; t < 16; ++t) {
                        if (t & (1 << i)) continue;
                        const int t1 = t | (1 << i);
                        u64 Av = A[t], Bv = A[t1];
                        Av = fma2(Bv, tnv, Av);
                        Bv = fma2(Av, sv,  Bv);
                        Av = fma2(Bv, tnv, Av);
                        A[t] = Av; A[t1] = Bv;
                    }
                }

                {
                    int j = jb;
                    #pragma unroll
                    for (int u = 0; u < 8; ++u) {
                        const int g = u ^ (u >> 1);
                        sAmp[j]       = A[g];
                        sAmp[j ^ V15] = A[g ^ 15];
                        if (u < 7) {
                            const int un = u + 1;
                            const int c  = (un & 1) ? 0 : ((un & 2) ? 1 : 2);
                            j ^= mk[c];
                        }
                    }
                }
            }
        }
    }
    __syncthreads();

    // ---- expectation value ----
    const int ff = sC.ffin;
    float acc = 0.0f;
    #pragma unroll
    for (int k = 0; k < QDIM / NTHREADS; ++k) {
        int j = tid + k * NTHREADS;
        float2 a = sF2[j];
        float pr = a.x * a.x + a.y * a.y;
        acc += (__popc(ff & j) & 1) ? -pr : pr;
    }
    #pragma unroll
    for (int off = 16; off > 0; off >>= 1)
        acc += __shfl_down_sync(0xffffffffu, acc, off);
    if ((tid & 31) == 0) redbuf[tid >> 5] = acc;
    __syncthreads();
    if (tid < 32) {
        float t = (tid < NTHREADS / 32) ? redbuf[tid] : 0.0f;
        #pragma unroll
        for (int off = 8; off > 0; off >>= 1)
            t += __shfl_down_sync(0xffffffffu, t, off);
        if (tid == 0) out[b] = (t + 1.0f) * 0.5f;
    }
}

extern "C" void kernel_launch(void* const* d_in, const int* in_sizes, int n_in,
                              void* d_out, int out_size)
{
    const float* x      = (const float*)d_in[0];   // (2048, 14)
    const float* params = (const float*)d_in[1];   // (224,)
    float* out          = (float*)d_out;           // (2048,)
    (void)in_sizes; (void)n_in;

    qnn_setup<<<1, 512>>>(params);

    const size_t shmem = (size_t)QDIM * sizeof(u64);   // 128 KB
    cudaFuncSetAttribute(qnn_kernel,
                         cudaFuncAttributeMaxDynamicSharedMemorySize,
                         (int)shmem);
    qnn_kernel<<<out_size, NTHREADS, shmem>>>(x, out);
}

// round 11
// speedup vs baseline: 1.5208x; 1.0808x over previous
#include <cuda_runtime.h>

// QNNClassifier: 14-qubit statevector, BATCH=2048, DEPTH=8.
// One CTA/batch element; state = QDIM packed (re,im) u64 in smem (128 KB).
// CX deferred as GF(2) relabeling; per layer gates grouped 5+5+4 (same sigma
// frame => W=I and F_g.m_i = delta => ALL RZ phases of a layer commute with
// all other gates' RYs). So the ENTIRE layer's diagonal (14 RZ phases) is
// applied once in pass 1 (gates 5-13 contribute per-thread constants via two
// small parity-indexed tables); passes 2 and 3 are pure real-shear passes.
// RY gates = 3-shear packed-f32x2 butterflies, roles folded into constant
// sign bits. Coset addressing is bank-conflict-free (pivots>=4 + fixup).

#define NQ       14
#define QDIM     16384
#define DEPTH    8
#define NGATES   (DEPTH * NQ)   // 112
#define NPASSES  (DEPTH * 3)    // 24 (5+5+4 per layer)
#define NTHREADS 512

typedef unsigned long long u64;
typedef unsigned int u32;

struct __align__(16) Consts {
    int    piv[NPASSES][5];     // sorted pivot bits (pad 30)
    int    M[NPASSES][5];       // flip masks per gate
    int    F[NPASSES][5];       // parity masks per gate
    float  tq[NPASSES][5];      // tan(ty/4)
    float  sy[NPASSES][5];      // sin(ty/2)
    float  czH[NPASSES][5];     // cos(tz/2)
    float  szH[NPASSES][5];     // sin(tz/2)
    float  czF[NPASSES][5];     // cos(tz)
    float  szF[NPASSES][5];     // sin(tz)
    float2 T1[DEPTH][32];       // product of gates 5-9 half-angle factors per 5-bit parity
    float2 T2[DEPTH][16];       // product of gates 10-13 factors per 4-bit parity
    int    fixTab[NPASSES][16]; // low-nibble bank fixup
    int    fixShift[NPASSES];
    int    ffin;
};
__device__ Consts dC;

// ---------------- setup kernel (512 threads, 1 block) ----------------
__global__ void qnn_setup(const float* __restrict__ params)
{
    __shared__ int vg[NGATES], fg[NGATES];
    const int tid = threadIdx.x;

    if (tid == 0) {
        int v[NQ], f[NQ];
        #pragma unroll
        for (int q = 0; q < NQ; ++q) { v[q] = 1 << (NQ - 1 - q); f[q] = v[q]; }
        for (int l = 0; l < DEPTH; ++l) {
            for (int q = 0; q < NQ; ++q) { fg[l * NQ + q] = f[q]; vg[l * NQ + q] = v[q]; }
            for (int c = 0; c < NQ; ++c) {          // CX ring after the layer
                int t = (c + 1) % NQ;
                v[c] ^= v[t];
                f[t] ^= f[c];
            }
        }
        dC.ffin = f[0];
    }
    __syncthreads();

    if (tid < NGATES) {                              // per-gate constants
        int l = tid / NQ, q = tid % NQ;
        int grp  = (q < 5) ? 0 : (q < 10) ? 1 : 2;
        int base = (grp == 0) ? 0 : (grp == 1) ? 5 : 10;
        int p = l * 3 + grp, i = q - base;
        float tz = params[2 * tid];
        float ty = params[2 * tid + 1];
        dC.tq[p][i] = tanf(0.25f * ty);
        dC.sy[p][i] = sinf(0.5f * ty);
        float sH, cH, sF, cF;
        sincosf(0.5f * tz, &sH, &cH);
        sincosf(tz, &sF, &cF);
        dC.czH[p][i] = cH; dC.szH[p][i] = sH;
        dC.czF[p][i] = cF; dC.szF[p][i] = sF;
        dC.F[p][i]   = fg[tid];
        dC.M[p][i]   = vg[tid];
    }

    // T1: per-layer product of gates 5..9 half-angle factors, all 32 sign combos
    if (tid < DEPTH * 32) {
        int l = tid >> 5, m = tid & 31;
        float zr = 1.0f, zi = 0.0f;
        for (int i = 0; i < 5; ++i) {
            float tz = params[2 * (l * NQ + 5 + i)];
            float s, c; sincosf(0.5f * tz, &s, &c);
            float sn = ((m >> i) & 1) ? s : -s;
            float t = zr * c - zi * sn;
            zi = zi * c + zr * sn;
            zr = t;
        }
        dC.T1[l][m] = make_float2(zr, zi);
    }
    // T2: gates 10..13, 16 combos
    if (tid >= 256 && tid < 256 + DEPTH * 16) {
        int idx = tid - 256;
        int l = idx >> 4, m = idx & 15;
        float zr = 1.0f, zi = 0.0f;
        for (int i = 0; i < 4; ++i) {
            float tz = params[2 * (l * NQ + 10 + i)];
            float s, c; sincosf(0.5f * tz, &s, &c);
            float sn = ((m >> i) & 1) ? s : -s;
            float t = zr * c - zi * sn;
            zi = zi * c + zr * sn;
            zr = t;
        }
        dC.T2[l][m] = make_float2(zr, zi);
    }

    if (tid < NPASSES) {                             // pass geometry
        int l = tid / 3, grp = tid % 3;
        int cnt  = (grp == 2) ? 4 : 5;
        int base = (grp == 0) ? 0 : (grp == 1) ? 5 : 10;
        int m[5] = {0, 0, 0, 0, 0};
        for (int i = 0; i < cnt; ++i) m[i] = vg[l * NQ + base + i];

        // GF(2) elimination; prefer pivot bits >= 4 (bank-friendly)
        int u[5], bp[5];
        for (int i = 0; i < cnt; ++i) {
            u[i] = m[i];
            for (int j = 0; j < i; ++j)
                if ((u[i] >> bp[j]) & 1) u[i] ^= u[j];
            int hi = u[i] & ~0xF;
            bp[i] = hi ? (31 - __clz(hi)) : (31 - __clz(u[i]));
            for (int j = 0; j < i; ++j)
                if ((u[j] >> bp[i]) & 1) u[j] ^= u[i];
        }
        for (int a = 0; a < cnt - 1; ++a)            // sort ascending
            for (int bq = 0; bq < cnt - 1 - a; ++bq)
                if (bp[bq] > bp[bq + 1]) { int t = bp[bq]; bp[bq] = bp[bq + 1]; bp[bq + 1] = t; }
        for (int i = 0; i < 5; ++i) dC.piv[tid][i] = (i < cnt) ? bp[i] : 30;

        // low-nibble fixup: copy spare rep-bits into pivot positions < 4
        int lowPiv[4], k = 0;
        for (int i = 0; i < cnt; ++i)
            if (bp[i] < 4) lowPiv[k++] = bp[i];
        dC.fixShift[tid] = 4 - k;
        for (int v = 0; v < 16; ++v) {
            int fv = 0;
            for (int i = 0; i < k; ++i)
                if ((v >> i) & 1) fv |= 1 << lowPiv[i];
            dC.fixTab[tid][v] = fv;
        }
    }
}

// ---------------- helpers ----------------
__device__ __forceinline__ u64 fma2(u64 a, u64 b, u64 c) {
    u64 d; asm("fma.rn.f32x2 %0, %1, %2, %3;" : "=l"(d) : "l"(a), "l"(b), "l"(c));
    return d;
}
__device__ __forceinline__ u64 pk(float lo, float hi) {
    u64 d; asm("mov.b64 %0, {%1, %2};" : "=l"(d) : "f"(lo), "f"(hi));
    return d;
}
__device__ __forceinline__ u64 splat_sgn(float v, u32 sb) {
    u32 b = __float_as_uint(v) ^ sb;
    return ((u64)b << 32) | (u64)b;
}
__device__ __forceinline__ float fsgn(float v, u32 sb) {
    return __int_as_float(__float_as_int(v) ^ sb);
}

// insert zero bits at 5 sorted pivot positions (pad pivot 30 = no-op)
__device__ __forceinline__ int expand5(int p, const int* bp)
{
    #pragma unroll
    for (int i = 0; i < 5; ++i) {
        int m = (1 << bp[i]) - 1;
        p = ((p & ~m) << 1) | (p & m);
    }
    return p;
}

// ---------------- main kernel ----------------
__global__ __launch_bounds__(NTHREADS, 1)
void qnn_kernel(const float* __restrict__ x, float* __restrict__ out)
{
    extern __shared__ u64 sAmp[];                  // [QDIM] packed (re,im)
    float2* sF2 = (float2*)sAmp;

    __shared__ Consts sC;
    __shared__ float cq[NQ], sq[NQ];
    __shared__ float tabLo[128], tabHi[128];
    __shared__ float redbuf[NTHREADS / 32];

    const int tid = threadIdx.x;
    const int b   = blockIdx.x;

    {   // copy constants to smem
        const int n = (int)(sizeof(Consts) / 4);
        const int* src = (const int*)&dC;
        int* dst = (int*)&sC;
        for (int i = tid; i < n; i += NTHREADS) dst[i] = src[i];
    }

    if (tid < NQ) {
        float ang = x[b * NQ + tid] * 1.57079632679489662f;
        float s, c;
        sincosf(ang, &s, &c);
        cq[tid] = c;
        sq[tid] = s;
    }
    __syncthreads();

    // product-state tables (initial RY layer on |0...0>)
    if (tid < 128) {
        float p = 1.0f;
        #pragma unroll
        for (int k = 0; k < 7; ++k)
            p *= ((tid >> k) & 1) ? sq[NQ - 1 - k] : cq[NQ - 1 - k];
        tabLo[tid] = p;
    } else if (tid < 256) {
        int m = tid - 128;
        float p = 1.0f;
        #pragma unroll
        for (int k = 0; k < 7; ++k)
            p *= ((m >> k) & 1) ? sq[6 - k] : cq[6 - k];
        tabHi[m] = p;
    }
    __syncthreads();

    #pragma unroll
    for (int k = 0; k < QDIM / NTHREADS; ++k) {
        int j = tid + k * NTHREADS;
        sAmp[j] = (u64)__float_as_uint(tabHi[j >> 7] * tabLo[j & 127]);
    }

    // ---- 24 passes (per layer: [D_layer + 5 RY], [5 RY], [4 RY]) ----
    for (int p = 0; p < NPASSES; ++p) {
        __syncthreads();
        const int l   = p / 3;
        const int grp = p - l * 3;

        if (grp == 0) {
            // ======== pass 1: full-layer diagonal + 5 shears, 32-amp coset ========
            int mk[5];
            #pragma unroll
            for (int i = 0; i < 5; ++i) mk[i] = sC.M[p][i];

            int jb = expand5(tid, sC.piv[p]);
            jb ^= sC.fixTab[p][(tid >> sC.fixShift[p]) & 15];

            int bb = 0;
            #pragma unroll
            for (int g = 0; g < 5; ++g)
                bb |= (__popc(sC.F[p][g] & jb) & 1) << g;
            int bb1 = 0;
            #pragma unroll
            for (int g = 0; g < 5; ++g)
                bb1 |= (__popc(sC.F[p + 1][g] & jb) & 1) << g;
            int bb2 = 0;
            #pragma unroll
            for (int g = 0; g < 4; ++g)
                bb2 |= (__popc(sC.F[p + 2][g] & jb) & 1) << g;

            // z0 = (own 5 half-angle factors, role-signed) * T1[bb1] * T2[bb2]
            float zr, zi;
            {
                zr = sC.czH[p][0];
                zi = -fsgn(sC.szH[p][0], (u32)(bb & 1) << 31);
                #pragma unroll
                for (int k = 1; k < 5; ++k) {
                    float c  = sC.czH[p][k];
                    float sn = -fsgn(sC.szH[p][k], (u32)((bb >> k) & 1) << 31);
                    float t  = zr * c - zi * sn;
                    zi = zi * c + zr * sn;
                    zr = t;
                }
                float2 t1 = sC.T1[l][bb1];
                float t  = zr * t1.x - zi * t1.y;
                zi = zi * t1.x + zr * t1.y;
                zr = t;
                float2 t2 = sC.T2[l][bb2];
                t  = zr * t2.x - zi * t2.y;
                zi = zi * t2.x + zr * t2.y;
                zr = t;
            }
            // full-angle step constants (walk bits 0..3) + gate-4 ratio, role-signed
            float cF0 = sC.czF[p][0], sF0 = fsgn(sC.szF[p][0], (u32)(bb & 1) << 31);
            float cF1 = sC.czF[p][1], sF1 = fsgn(sC.szF[p][1], (u32)((bb >> 1) & 1) << 31);
            float cF2 = sC.czF[p][2], sF2v = fsgn(sC.szF[p][2], (u32)((bb >> 2) & 1) << 31);
            float cF3 = sC.czF[p][3], sF3 = fsgn(sC.szF[p][3], (u32)((bb >> 3) & 1) << 31);
            float cF4 = sC.czF[p][4], sF4 = fsgn(sC.szF[p][4], (u32)((bb >> 4) & 1) << 31);

            // chain B = chain A * e^{role-signed i tz4}
            float zbr = zr * cF4 - zi * sF4;
            float zbi = zi * cF4 + zr * sF4;

            // dual 4-bit Gray walk: slot g (bit4=0) with zA, slot g|16 with zB
            u64 A[32];
            {
                int j = jb;
                const int m4 = mk[4];
                #pragma unroll
                for (int u = 0; u < 16; ++u) {
                    const int g = u ^ (u >> 1);
                    float2 a  = sF2[j];
                    float2 c2 = sF2[j ^ m4];
                    A[g]      = pk(a.x * zr - a.y * zi,   a.y * zr + a.x * zi);
                    A[g | 16] = pk(c2.x * zbr - c2.y * zbi, c2.y * zbr + c2.x * zbi);
                    if (u < 15) {
                        const int un = u + 1;
                        const int c  = (un & 1) ? 0 : ((un & 2) ? 1 : ((un & 4) ? 2 : 3));
                        const int gn = ((un ^ (un >> 1)) >> c) & 1;
                        float cc = (c == 0) ? cF0 : (c == 1) ? cF1 : (c == 2) ? cF2 : cF3;
                        float ss = (c == 0) ? sF0 : (c == 1) ? sF1 : (c == 2) ? sF2v : sF3;
                        if (!gn) ss = -ss;
                        float t = zr * cc - zi * ss;
                        zi = zi * cc + zr * ss;
                        zr = t;
                        t   = zbr * cc - zbi * ss;
                        zbi = zbi * cc + zbr * ss;
                        zbr = t;
                        j ^= mk[c];
                    }
                }
            }

            // 5 RY gates as 3-shear butterflies
            #pragma unroll
            for (int i = 0; i < 5; ++i) {
                const u32 sg  = ((u32)((bb >> i) & 1)) << 31;
                const u64 tnv = splat_sgn(sC.tq[p][i], sg ^ 0x80000000u);
                const u64 sv  = splat_sgn(sC.sy[p][i], sg);
                #pragma unroll
                for (int t = 0; t < 32; ++t) {
                    if (t & (1 << i)) continue;
                    const int t1 = t | (1 << i);
                    u64 Av = A[t], Bv = A[t1];
                    Av = fma2(Bv, tnv, Av);
                    Bv = fma2(Av, sv,  Bv);
                    Av = fma2(Bv, tnv, Av);
                    A[t] = Av; A[t1] = Bv;
                }
            }

            // dual Gray store
            {
                int j = jb;
                const int m4 = mk[4];
                #pragma unroll
                for (int u = 0; u < 16; ++u) {
                    const int g = u ^ (u >> 1);
                    sAmp[j]      = A[g];
                    sAmp[j ^ m4] = A[g | 16];
                    if (u < 15) {
                        const int un = u + 1;
                        const int c  = (un & 1) ? 0 : ((un & 2) ? 1 : ((un & 4) ? 2 : 3));
                        j ^= mk[c];
                    }
                }
            }
        } else if (grp == 1) {
            // ======== pass 2: pure shear, 5 gates, 32-amp coset ========
            int mk[5];
            #pragma unroll
            for (int i = 0; i < 5; ++i) mk[i] = sC.M[p][i];

            int jb = expand5(tid, sC.piv[p]);
            jb ^= sC.fixTab[p][(tid >> sC.fixShift[p]) & 15];

            int bb = 0;
            #pragma unroll
            for (int g = 0; g < 5; ++g)
                bb |= (__popc(sC.F[p][g] & jb) & 1) << g;

            u64 A[32];
            {
                int j = jb;
                const int m4 = mk[4];
                #pragma unroll
                for (int u = 0; u < 16; ++u) {
                    const int g = u ^ (u >> 1);
                    A[g]      = sAmp[j];
                    A[g | 16] = sAmp[j ^ m4];
                    if (u < 15) {
                        const int un = u + 1;
                        const int c  = (un & 1) ? 0 : ((un & 2) ? 1 : ((un & 4) ? 2 : 3));
                        j ^= mk[c];
                    }
                }
            }

            #pragma unroll
            for (int i = 0; i < 5; ++i) {
                const u32 sg  = ((u32)((bb >> i) & 1)) << 31;
                const u64 tnv = splat_sgn(sC.tq[p][i], sg ^ 0x80000000u);
                const u64 sv  = splat_sgn(sC.sy[p][i], sg);
                #pragma unroll
                for (int t = 0; t < 32; ++t) {
                    if (t & (1 << i)) continue;
                    const int t1 = t | (1 << i);
                    u64 Av = A[t], Bv = A[t1];
                    Av = fma2(Bv, tnv, Av);
                    Bv = fma2(Av, sv,  Bv);
                    Av = fma2(Bv, tnv, Av);
                    A[t] = Av; A[t1] = Bv;
                }
            }

            {
                int j = jb;
                const int m4 = mk[4];
                #pragma unroll
                for (int u = 0; u < 16; ++u) {
                    const int g = u ^ (u >> 1);
                    sAmp[j]      = A[g];
                    sAmp[j ^ m4] = A[g | 16];
                    if (u < 15) {
                        const int un = u + 1;
                        const int c  = (un & 1) ? 0 : ((un & 2) ? 1 : ((un & 4) ? 2 : 3));
                        j ^= mk[c];
                    }
                }
            }
        } else {
            // ======== pass 3: pure shear, 4 gates, two 16-amp cosets ========
            int mk[4];
            #pragma unroll
            for (int i = 0; i < 4; ++i) mk[i] = sC.M[p][i];
            const int fsh = sC.fixShift[p];

            #pragma unroll
            for (int kk = 0; kk < 2; ++kk) {
                const int pp = tid + kk * NTHREADS;
                int jb = expand5(pp, sC.piv[p]);
                jb ^= sC.fixTab[p][(pp >> fsh) & 15];

                int bb = 0;
                #pragma unroll
                for (int g = 0; g < 4; ++g)
                    bb |= (__popc(sC.F[p][g] & jb) & 1) << g;

                u64 A[16];
                {
                    int j = jb;
                    #pragma unroll
                    for (int u = 0; u < 16; ++u) {
                        const int g = u ^ (u >> 1);
                        A[g] = sAmp[j];
                        if (u < 15) {
                            const int un = u + 1;
                            const int c  = (un & 1) ? 0 : ((un & 2) ? 1 : ((un & 4) ? 2 : 3));
                            j ^= mk[c];
                        }
                    }
                }

                #pragma unroll
                for (int i = 0; i < 4; ++i) {
                    const u32 sg  = ((u32)((bb >> i) & 1)) << 31;
                    const u64 tnv = splat_sgn(sC.tq[p][i], sg ^ 0x80000000u);
                    const u64 sv  = splat_sgn(sC.sy[p][i], sg);
                    #pragma unroll
                    for (int t = 0; t < 16; ++t) {
                        if (t & (1 << i)) continue;
                        const int t1 = t | (1 << i);
                        u64 Av = A[t], Bv = A[t1];
                        Av = fma2(Bv, tnv, Av);
                        Bv = fma2(Av, sv,  Bv);
                        Av = fma2(Bv, tnv, Av);
                        A[t] = Av; A[t1] = Bv;
                    }
                }

                {
                    int j = jb;
                    #pragma unroll
                    for (int u = 0; u < 16; ++u) {
                        const int g = u ^ (u >> 1);
                        sAmp[j] = A[g];
                        if (u < 15) {
                            const int un = u + 1;
                            const int c  = (un & 1) ? 0 : ((un & 2) ? 1 : ((un & 4) ? 2 : 3));
                            j ^= mk[c];
                        }
                    }
                }
            }
        }
    }
    __syncthreads();

    // ---- expectation value ----
    const int ff = sC.ffin;
    float acc = 0.0f;
    #pragma unroll
    for (int k = 0; k < QDIM / NTHREADS; ++k) {
        int j = tid + k * NTHREADS;
        float2 a = sF2[j];
        float pr = a.x * a.x + a.y * a.y;
        acc += (__popc(ff & j) & 1) ? -pr : pr;
    }
    #pragma unroll
    for (int off = 16; off > 0; off >>= 1)
        acc += __shfl_down_sync(0xffffffffu, acc, off);
    if ((tid & 31) == 0) redbuf[tid >> 5] = acc;
    __syncthreads();
    if (tid < 32) {
        float t = (tid < NTHREADS / 32) ? redbuf[tid] : 0.0f;
        #pragma unroll
        for (int off = 8; off > 0; off >>= 1)
            t += __shfl_down_sync(0xffffffffu, t, off);
        if (tid == 0) out[b] = (t + 1.0f) * 0.5f;
    }
}

extern "C" void kernel_launch(void* const* d_in, const int* in_sizes, int n_in,
                              void* d_out, int out_size)
{
    const float* x      = (const float*)d_in[0];   // (2048, 14)
    const float* params = (const float*)d_in[1];   // (224,)
    float* out          = (float*)d_out;           // (2048,)
    (void)in_sizes; (void)n_in;

    qnn_setup<<<1, 512>>>(params);

    const size_t shmem = (size_t)QDIM * sizeof(u64);   // 128 KB
    cudaFuncSetAttribute(qnn_kernel,
                         cudaFuncAttributeMaxDynamicSharedMemorySize,
                         (int)shmem);
    qnn_kernel<<<out_size, NTHREADS, shmem>>>(x, out);
}